// round 6
// baseline (speedup 1.0000x reference)
#include <cuda_runtime.h>
#include <cuda_bf16.h>

#define N_SAMPLE 12
#define D_FEAT 64
#define NODES_PER_WARP 4

__global__ void __launch_bounds__(256)
mean_agg_kernel(const float* __restrict__ feature,
                const int* __restrict__ neighbor_idx,
                float* __restrict__ out,
                int n_nodes) {
    int gwarp = (int)((blockIdx.x * (unsigned)blockDim.x + threadIdx.x) >> 5);
    int lane  = threadIdx.x & 31;
    int g     = lane >> 3;   // group 0..3 -> node within warp
    int lg    = lane & 7;    // lane in group: owns 8 floats (32 B) of the row

    int node = gwarp * NODES_PER_WARP + g;
    bool active = node < n_nodes;
    int node_c = active ? node : 0;   // clamp so inactive lanes load safely

    // Each group needs 12 indices: lanes 0..7 hold samples 0..7 (idx_a),
    // lanes 0..3 additionally hold samples 8..11 (idx_b).
    const int* ibase = neighbor_idx + (long long)node_c * N_SAMPLE;
    int idx_a = ibase[lg];
    int idx_b = (lg < 4) ? ibase[8 + lg] : 0;

    float a0=0.f,a1=0.f,a2=0.f,a3=0.f,a4=0.f,a5=0.f,a6=0.f,a7=0.f;

#pragma unroll
    for (int s = 0; s < N_SAMPLE; s++) {
        int src = g * 8 + (s < 8 ? s : s - 8);
        int id  = __shfl_sync(0xffffffffu, (s < 8) ? idx_a : idx_b, src);
        const float* fp = feature + (long long)id * D_FEAT + lg * 8;
        unsigned r0,r1,r2,r3,r4,r5,r6,r7;
        // 256-bit gather, pinned in L2 (feature reused ~6x per launch).
        asm volatile("ld.global.nc.L2::evict_last.v8.b32 "
                     "{%0,%1,%2,%3,%4,%5,%6,%7}, [%8];"
                     : "=r"(r0),"=r"(r1),"=r"(r2),"=r"(r3),
                       "=r"(r4),"=r"(r5),"=r"(r6),"=r"(r7)
                     : "l"(fp));
        a0 += __uint_as_float(r0); a1 += __uint_as_float(r1);
        a2 += __uint_as_float(r2); a3 += __uint_as_float(r3);
        a4 += __uint_as_float(r4); a5 += __uint_as_float(r5);
        a6 += __uint_as_float(r6); a7 += __uint_as_float(r7);
    }

    const float inv = 1.0f / (float)N_SAMPLE;
    if (active) {
        float* op = out + (long long)node * D_FEAT + lg * 8;
        unsigned w0 = __float_as_uint(a0 * inv), w1 = __float_as_uint(a1 * inv);
        unsigned w2 = __float_as_uint(a2 * inv), w3 = __float_as_uint(a3 * inv);
        unsigned w4 = __float_as_uint(a4 * inv), w5 = __float_as_uint(a5 * inv);
        unsigned w6 = __float_as_uint(a6 * inv), w7 = __float_as_uint(a7 * inv);
        // Streaming write-once output: don't let it evict feature lines.
        asm volatile("st.global.L2::evict_first.v8.b32 [%0], "
                     "{%1,%2,%3,%4,%5,%6,%7,%8};"
                     :: "l"(op),
                        "r"(w0),"r"(w1),"r"(w2),"r"(w3),
                        "r"(w4),"r"(w5),"r"(w6),"r"(w7)
                     : "memory");
    }
}

extern "C" void kernel_launch(void* const* d_in, const int* in_sizes, int n_in,
                              void* d_out, int out_size) {
    const float* feature      = (const float*)d_in[0];
    const int*   neighbor_idx = (const int*)d_in[1];
    float*       out          = (float*)d_out;

    int n_nodes = in_sizes[1] / N_SAMPLE;

    int warps  = (n_nodes + NODES_PER_WARP - 1) / NODES_PER_WARP;
    int blocks = (warps + 7) / 8;   // 8 warps (256 threads) per block
    mean_agg_kernel<<<blocks, 256>>>(feature, neighbor_idx, out, n_nodes);
}